// round 1
// baseline (speedup 1.0000x reference)
#include <cuda_runtime.h>
#include <math.h>
#include <stdint.h>

#define BB 512
#define TT 2048
#define DD 20
#define C0 32
#define C1 16
#define CH 256
#define NCHUNK ((BB*TT)/CH)     /* 4096 */
#define NTOT   ((double)(BB)*(double)(TT))

// ---------------- scratch (device globals; no allocation) ----------------
__device__ float4 g_h0[(size_t)NCHUNK * 8 * CH];   // [chunk][c4<8][t<256], 134MB
__device__ float4 g_h1[(size_t)NCHUNK * 4 * CH];   // [chunk][c4<4][t<256], 67MB
__device__ float  g_Weff[BB * DD * C0];            // [b][d][c]
__device__ float  g_Cb[BB * C0];                   // [b][c]
__device__ double g_stats[96];                     // [0:32) sum0 [32:64) sq0 [64:80) sum1 [80:96) sq1
__device__ float4 g_dice0[C0];                     // {mean, rstd, alpha, 1-alpha}
__device__ float4 g_dice1[C1];

// ---------------- K0: per-batch folded weights + zero accumulators ----------------
__global__ void k_prep(const float* __restrict__ q, const float* __restrict__ W0,
                       const float* __restrict__ b0, float* __restrict__ out) {
    int b = blockIdx.x;
    int c = threadIdx.x;              // 32 threads
    if (b == 0) {
        for (int i = c; i < 96; i += 32) g_stats[i] = 0.0;
    }
    int gid = b * 32 + c;
    if (gid < BB * DD) out[gid] = 0.0f;

    float acc = b0[c];
#pragma unroll
    for (int d = 0; d < DD; d++) {
        float qd = q[b * DD + d];
        float wA = W0[(d)          * C0 + c];
        float wB = W0[(DD + d)     * C0 + c];
        float wC = W0[(2 * DD + d) * C0 + c];
        float wD = W0[(3 * DD + d) * C0 + c];
        g_Weff[(b * DD + d) * C0 + c] = wB - wC + qd * wD;
        acc += qd * (wA + wC);
    }
    g_Cb[b * C0 + c] = acc;
}

// ---------------- K1: h0 = keys @ Weff[b] + Cb[b]; store + stats ----------------
__global__ void __launch_bounds__(CH) k_h0(const float* __restrict__ keys) {
    int blk = blockIdx.x;             // 1024 blocks: 2 per batch, 4 chunks each
    int b   = blk >> 1;
    int ck0 = (blk & 1) * 4;
    int tid = threadIdx.x;
    int lane = tid & 31, warp = tid >> 5;

    __shared__ float4 sW[DD * 8];     // Weff [d][c4]
    __shared__ float4 sC[8];
    __shared__ float4 sK4[CH * DD / 4];  // 20KB key tile
    __shared__ float  sRed[8 * 64];

    for (int i = tid; i < DD * 8; i += CH) {
        const float* p = &g_Weff[b * DD * C0 + i * 4];
        sW[i] = make_float4(p[0], p[1], p[2], p[3]);
    }
    if (tid < 8) {
        const float* p = &g_Cb[b * C0 + tid * 4];
        sC[tid] = make_float4(p[0], p[1], p[2], p[3]);
    }

    float4 s0[8], q0[8];
#pragma unroll
    for (int i = 0; i < 8; i++) { s0[i] = make_float4(0,0,0,0); q0[i] = make_float4(0,0,0,0); }

    const float* sKf = (const float*)sK4;

    for (int lc = 0; lc < 4; lc++) {
        size_t chunk = (size_t)b * 8 + ck0 + lc;
        __syncthreads();
        const float4* src = (const float4*)(keys + chunk * CH * DD);
#pragma unroll
        for (int i = 0; i < 5; i++) sK4[tid + i * CH] = src[tid + i * CH];
        __syncthreads();

        float kk[DD];
#pragma unroll
        for (int j = 0; j < 5; j++)
            ((float4*)kk)[j] = ((const float4*)(sKf + tid * DD))[j];

        float4 acc[8];
#pragma unroll
        for (int i = 0; i < 8; i++) acc[i] = sC[i];
#pragma unroll
        for (int d = 0; d < DD; d++) {
            float kd = kk[d];
#pragma unroll
            for (int i = 0; i < 8; i++) {
                float4 w = sW[d * 8 + i];
                acc[i].x = fmaf(kd, w.x, acc[i].x);
                acc[i].y = fmaf(kd, w.y, acc[i].y);
                acc[i].z = fmaf(kd, w.z, acc[i].z);
                acc[i].w = fmaf(kd, w.w, acc[i].w);
            }
        }
        float4* dst = &g_h0[chunk * 8 * CH];
#pragma unroll
        for (int i = 0; i < 8; i++) dst[i * CH + tid] = acc[i];
#pragma unroll
        for (int i = 0; i < 8; i++) {
            s0[i].x += acc[i].x; s0[i].y += acc[i].y; s0[i].z += acc[i].z; s0[i].w += acc[i].w;
            q0[i].x = fmaf(acc[i].x, acc[i].x, q0[i].x);
            q0[i].y = fmaf(acc[i].y, acc[i].y, q0[i].y);
            q0[i].z = fmaf(acc[i].z, acc[i].z, q0[i].z);
            q0[i].w = fmaf(acc[i].w, acc[i].w, q0[i].w);
        }
    }

    float vals[64];
#pragma unroll
    for (int i = 0; i < 8; i++) {
        vals[i*4+0] = s0[i].x; vals[i*4+1] = s0[i].y; vals[i*4+2] = s0[i].z; vals[i*4+3] = s0[i].w;
        vals[32+i*4+0] = q0[i].x; vals[32+i*4+1] = q0[i].y; vals[32+i*4+2] = q0[i].z; vals[32+i*4+3] = q0[i].w;
    }
#pragma unroll
    for (int v = 0; v < 64; v++) {
#pragma unroll
        for (int off = 16; off > 0; off >>= 1)
            vals[v] += __shfl_xor_sync(0xffffffffu, vals[v], off);
    }
    if (lane == 0) {
#pragma unroll
        for (int v = 0; v < 64; v++) sRed[warp * 64 + v] = vals[v];
    }
    __syncthreads();
    if (tid < 64) {
        float s = 0.f;
#pragma unroll
        for (int w = 0; w < 8; w++) s += sRed[w * 64 + tid];
        atomicAdd(&g_stats[tid], (double)s);
    }
}

// ---------------- K2: finalize layer-0 batchnorm ----------------
__global__ void k_fin0(const float* __restrict__ a0) {
    int c = threadIdx.x;  // 32
    double m = g_stats[c] / NTOT;
    double v = g_stats[32 + c] / NTOT - m * m;
    float rstd = (float)(1.0 / sqrt(v + 1e-9));
    float al = a0[c];
    g_dice0[c] = make_float4((float)m, rstd, al, 1.0f - al);
}

// ---------------- K3: dice0(h0) @ W1 + b1; store h1 + stats ----------------
__global__ void __launch_bounds__(CH) k_h1(const float* __restrict__ W1,
                                           const float* __restrict__ b1) {
    int blk = blockIdx.x;             // 1024 blocks × 4 chunks
    int tid = threadIdx.x;
    int lane = tid & 31, warp = tid >> 5;

    __shared__ float4 sW1[C0 * 4];    // [d<32][c4<4]
    __shared__ float4 sB1[4];
    __shared__ float4 sD0[C0];
    __shared__ float  sRed[8 * 32];

    for (int i = tid; i < C0 * 4; i += CH) sW1[i] = ((const float4*)W1)[i];
    if (tid < 4)  sB1[tid] = ((const float4*)b1)[tid];
    if (tid < C0) sD0[tid] = g_dice0[tid];
    __syncthreads();

    float4 s1[4], q1[4];
#pragma unroll
    for (int i = 0; i < 4; i++) { s1[i] = make_float4(0,0,0,0); q1[i] = make_float4(0,0,0,0); }

    for (int lc = 0; lc < 4; lc++) {
        size_t chunk = (size_t)blk * 4 + lc;
        const float4* srcb = &g_h0[chunk * 8 * CH];
        float x[C0];
#pragma unroll
        for (int i = 0; i < 8; i++) ((float4*)x)[i] = srcb[i * CH + tid];

        float4 acc[4];
#pragma unroll
        for (int i = 0; i < 4; i++) acc[i] = sB1[i];
#pragma unroll
        for (int d = 0; d < C0; d++) {
            float4 pr = sD0[d];
            float xn = (x[d] - pr.x) * pr.y;
            float p  = 1.0f / (1.0f + __expf(-xn));
            float hd = x[d] * (pr.z + p * pr.w);
#pragma unroll
            for (int i = 0; i < 4; i++) {
                float4 w = sW1[d * 4 + i];
                acc[i].x = fmaf(hd, w.x, acc[i].x);
                acc[i].y = fmaf(hd, w.y, acc[i].y);
                acc[i].z = fmaf(hd, w.z, acc[i].z);
                acc[i].w = fmaf(hd, w.w, acc[i].w);
            }
        }
        float4* dst = &g_h1[chunk * 4 * CH];
#pragma unroll
        for (int i = 0; i < 4; i++) dst[i * CH + tid] = acc[i];
#pragma unroll
        for (int i = 0; i < 4; i++) {
            s1[i].x += acc[i].x; s1[i].y += acc[i].y; s1[i].z += acc[i].z; s1[i].w += acc[i].w;
            q1[i].x = fmaf(acc[i].x, acc[i].x, q1[i].x);
            q1[i].y = fmaf(acc[i].y, acc[i].y, q1[i].y);
            q1[i].z = fmaf(acc[i].z, acc[i].z, q1[i].z);
            q1[i].w = fmaf(acc[i].w, acc[i].w, q1[i].w);
        }
    }

    float vals[32];
#pragma unroll
    for (int i = 0; i < 4; i++) {
        vals[i*4+0] = s1[i].x; vals[i*4+1] = s1[i].y; vals[i*4+2] = s1[i].z; vals[i*4+3] = s1[i].w;
        vals[16+i*4+0] = q1[i].x; vals[16+i*4+1] = q1[i].y; vals[16+i*4+2] = q1[i].z; vals[16+i*4+3] = q1[i].w;
    }
#pragma unroll
    for (int v = 0; v < 32; v++) {
#pragma unroll
        for (int off = 16; off > 0; off >>= 1)
            vals[v] += __shfl_xor_sync(0xffffffffu, vals[v], off);
    }
    if (lane == 0) {
#pragma unroll
        for (int v = 0; v < 32; v++) sRed[warp * 32 + v] = vals[v];
    }
    __syncthreads();
    if (tid < 32) {
        float s = 0.f;
#pragma unroll
        for (int w = 0; w < 8; w++) s += sRed[w * 32 + tid];
        atomicAdd(&g_stats[64 + tid], (double)s);
    }
}

// ---------------- K4: finalize layer-1 batchnorm ----------------
__global__ void k_fin1(const float* __restrict__ a1) {
    int c = threadIdx.x;  // 16
    double m = g_stats[64 + c] / NTOT;
    double v = g_stats[80 + c] / NTOT - m * m;
    float rstd = (float)(1.0 / sqrt(v + 1e-9));
    float al = a1[c];
    g_dice1[c] = make_float4((float)m, rstd, al, 1.0f - al);
}

// ---------------- K5: score = dice1(h1)@wk + bk; out[b] += score * keys ----------------
__global__ void __launch_bounds__(CH) k_out(const float* __restrict__ keys,
                                            const float* __restrict__ wk,
                                            const float* __restrict__ bk,
                                            float* __restrict__ out) {
    int blk = blockIdx.x;             // 1024: 2 blocks per batch
    int b   = blk >> 1;
    int ck0 = (blk & 1) * 4;
    int tid = threadIdx.x;
    int lane = tid & 31, warp = tid >> 5;

    __shared__ float4 sK4[CH * DD / 4];
    __shared__ float4 sD1[C1];
    __shared__ float  sWk[C1];
    __shared__ float  sBk;
    __shared__ float  sRed[8 * DD];

    if (tid < C1) { sD1[tid] = g_dice1[tid]; sWk[tid] = wk[tid]; }
    if (tid == 0) sBk = bk[0];

    const float* sKf = (const float*)sK4;
    float accd[DD];
#pragma unroll
    for (int d = 0; d < DD; d++) accd[d] = 0.f;

    for (int lc = 0; lc < 4; lc++) {
        size_t chunk = (size_t)b * 8 + ck0 + lc;
        __syncthreads();
        const float4* src = (const float4*)(keys + chunk * CH * DD);
#pragma unroll
        for (int i = 0; i < 5; i++) sK4[tid + i * CH] = src[tid + i * CH];
        __syncthreads();

        float y[C1];
        const float4* hb = &g_h1[chunk * 4 * CH];
#pragma unroll
        for (int i = 0; i < 4; i++) ((float4*)y)[i] = hb[i * CH + tid];

        float score = sBk;
#pragma unroll
        for (int c = 0; c < C1; c++) {
            float4 pr = sD1[c];
            float xn = (y[c] - pr.x) * pr.y;
            float p  = 1.0f / (1.0f + __expf(-xn));
            float hd = y[c] * (pr.z + p * pr.w);
            score = fmaf(hd, sWk[c], score);
        }

        float kk[DD];
#pragma unroll
        for (int j = 0; j < 5; j++)
            ((float4*)kk)[j] = ((const float4*)(sKf + tid * DD))[j];
#pragma unroll
        for (int d = 0; d < DD; d++) accd[d] = fmaf(score, kk[d], accd[d]);
    }

#pragma unroll
    for (int v = 0; v < DD; v++) {
#pragma unroll
        for (int off = 16; off > 0; off >>= 1)
            accd[v] += __shfl_xor_sync(0xffffffffu, accd[v], off);
    }
    if (lane == 0) {
#pragma unroll
        for (int v = 0; v < DD; v++) sRed[warp * DD + v] = accd[v];
    }
    __syncthreads();
    if (tid < DD) {
        float s = 0.f;
#pragma unroll
        for (int w = 0; w < 8; w++) s += sRed[w * DD + tid];
        atomicAdd(&out[b * DD + tid], s);
    }
}

// ---------------- launch ----------------
extern "C" void kernel_launch(void* const* d_in, const int* in_sizes, int n_in,
                              void* d_out, int out_size) {
    const float* keys = (const float*)d_in[0];
    const float* q    = (const float*)d_in[1];
    /* d_in[2] = mask: dead in the reference (unmasked scores are used) */
    const float* W0   = (const float*)d_in[3];
    const float* b0   = (const float*)d_in[4];
    const float* a0   = (const float*)d_in[5];
    const float* W1   = (const float*)d_in[6];
    const float* b1   = (const float*)d_in[7];
    const float* a1   = (const float*)d_in[8];
    const float* wk   = (const float*)d_in[9];
    const float* bk   = (const float*)d_in[10];
    float* out = (float*)d_out;

    k_prep<<<BB, 32>>>(q, W0, b0, out);
    k_h0  <<<1024, CH>>>(keys);
    k_fin0<<<1, 32>>>(a0);
    k_h1  <<<1024, CH>>>(W1, b1);
    k_fin1<<<1, 16>>>(a1);
    k_out <<<1024, CH>>>(keys, wk, bk, out);
}

// round 3
// speedup vs baseline: 1.0934x; 1.0934x over previous
#include <cuda_runtime.h>
#include <math.h>
#include <stdint.h>

#define BB 512
#define TT 2048
#define DD 20
#define C0 32
#define C1 16
#define CH 256
#define NCHUNK ((BB*TT)/CH)     /* 4096 */
#define NTOT   ((double)(BB)*(double)(TT))

// ---------------- scratch (device globals; no allocation) ----------------
__device__ float4 g_h0[(size_t)NCHUNK * 8 * CH];   // [chunk][c4<8][t<256]
__device__ float4 g_h1[(size_t)NCHUNK * 4 * CH];   // [chunk][c4<4][t<256]
__device__ float  g_Weff[BB * DD * C0];            // [b][d][c]
__device__ float  g_Cb[BB * C0];                   // [b][c]
__device__ double g_stats[96];                     // [0:32) s0 [32:64) q0 [64:80) s1 [80:96) q1
__device__ float4 g_dice0[C0];                     // {mean, rstd, alpha, 1-alpha}
__device__ float4 g_dice1[C1];

#define F4Z make_float4(0.f,0.f,0.f,0.f)
// NOTE: macro params must not collide with float4 member names (x/y/z/w)!
#define F4FMA(acc_,wv_,kk_) {acc_.x=fmaf((kk_),(wv_).x,acc_.x);acc_.y=fmaf((kk_),(wv_).y,acc_.y);acc_.z=fmaf((kk_),(wv_).z,acc_.z);acc_.w=fmaf((kk_),(wv_).w,acc_.w);}
#define F4ADD(acc_,bv_)     {acc_.x+=(bv_).x;acc_.y+=(bv_).y;acc_.z+=(bv_).z;acc_.w+=(bv_).w;}
#define F4SQA(acc_,bv_)     {acc_.x=fmaf((bv_).x,(bv_).x,acc_.x);acc_.y=fmaf((bv_).y,(bv_).y,acc_.y);acc_.z=fmaf((bv_).z,(bv_).z,acc_.z);acc_.w=fmaf((bv_).w,(bv_).w,acc_.w);}
#define SHRED(vv_)          {for(int o_=16;o_>0;o_>>=1){vv_.x+=__shfl_xor_sync(0xffffffffu,vv_.x,o_);vv_.y+=__shfl_xor_sync(0xffffffffu,vv_.y,o_);vv_.z+=__shfl_xor_sync(0xffffffffu,vv_.z,o_);vv_.w+=__shfl_xor_sync(0xffffffffu,vv_.w,o_);}}

__device__ __forceinline__ float dice_f(float x, float4 pr) {
    float xn = (x - pr.x) * pr.y;
    float p  = 1.0f / (1.0f + __expf(-xn));
    return x * (pr.z + p * pr.w);
}

// stage one 256x20 key chunk into padded smem (row stride 21 -> conflict-free)
__device__ __forceinline__ void stage_keys(float* sK, const float* __restrict__ keys,
                                           size_t chunk, int tid) {
    const float4* src = (const float4*)(keys + chunk * (size_t)(CH * DD));
#pragma unroll
    for (int i = 0; i < 5; i++) {
        float4 t = src[tid + i * CH];
        int f = tid + i * CH;
        int r = f / 5;
        int c = (f - r * 5) * 4;
        float* p = &sK[r * 21 + c];
        p[0] = t.x; p[1] = t.y; p[2] = t.z; p[3] = t.w;
    }
}

// ---------------- K0: per-batch folded weights + zero accumulators ----------------
__global__ void k_prep(const float* __restrict__ q, const float* __restrict__ W0,
                       const float* __restrict__ b0, float* __restrict__ out) {
    int b = blockIdx.x;
    int c = threadIdx.x;              // 32 threads
    if (b == 0) {
        for (int i = c; i < 96; i += 32) g_stats[i] = 0.0;
    }
    int gid = b * 32 + c;
    if (gid < BB * DD) out[gid] = 0.0f;

    float acc = b0[c];
#pragma unroll
    for (int d = 0; d < DD; d++) {
        float qd = q[b * DD + d];
        float wA = W0[(d)          * C0 + c];
        float wB = W0[(DD + d)     * C0 + c];
        float wC = W0[(2 * DD + d) * C0 + c];
        float wD = W0[(3 * DD + d) * C0 + c];
        g_Weff[(b * DD + d) * C0 + c] = wB - wC + qd * wD;
        acc += qd * (wA + wC);
    }
    g_Cb[b * C0 + c] = acc;
}

// ---------------- K1: h0 = keys @ Weff[b] + Cb[b]; store + stats ----------------
__global__ void __launch_bounds__(CH, 2) k_h0(const float* __restrict__ keys) {
    int blk = blockIdx.x;             // 1024 blocks: 2 per batch, 4 chunks each
    int b   = blk >> 1;
    int ck0 = (blk & 1) * 4;
    int tid = threadIdx.x;
    int lane = tid & 31, warp = tid >> 5;

    __shared__ float4 sW[DD * 8];     // Weff [d][c4]
    __shared__ float4 sC[8];
    __shared__ float  sK[CH * 21];    // padded key tile
    __shared__ float4 sRed[8 * 16];   // per-warp: 8 s + 8 q float4s

    for (int i = tid; i < DD * 8; i += CH)
        sW[i] = ((const float4*)(&g_Weff[b * DD * C0]))[i];
    if (tid < 8)
        sC[tid] = ((const float4*)(&g_Cb[b * C0]))[tid];

    float4 s0=F4Z,s1=F4Z,s2=F4Z,s3=F4Z,s4=F4Z,s5=F4Z,s6=F4Z,s7=F4Z;
    float4 q0=F4Z,q1=F4Z,q2=F4Z,q3=F4Z,q4=F4Z,q5=F4Z,q6=F4Z,q7=F4Z;

    for (int lc = 0; lc < 4; lc++) {
        size_t chunk = (size_t)b * 8 + ck0 + lc;
        __syncthreads();
        stage_keys(sK, keys, chunk, tid);
        __syncthreads();

        float4 a0=sC[0],a1=sC[1],a2=sC[2],a3=sC[3],a4=sC[4],a5=sC[5],a6=sC[6],a7=sC[7];
#pragma unroll
        for (int d = 0; d < DD; d++) {
            float kd = sK[tid * 21 + d];
            F4FMA(a0, sW[d*8+0], kd); F4FMA(a1, sW[d*8+1], kd);
            F4FMA(a2, sW[d*8+2], kd); F4FMA(a3, sW[d*8+3], kd);
            F4FMA(a4, sW[d*8+4], kd); F4FMA(a5, sW[d*8+5], kd);
            F4FMA(a6, sW[d*8+6], kd); F4FMA(a7, sW[d*8+7], kd);
        }
        float4* dst = &g_h0[chunk * 8 * CH];
        dst[0*CH+tid]=a0; dst[1*CH+tid]=a1; dst[2*CH+tid]=a2; dst[3*CH+tid]=a3;
        dst[4*CH+tid]=a4; dst[5*CH+tid]=a5; dst[6*CH+tid]=a6; dst[7*CH+tid]=a7;

        F4ADD(s0,a0); F4ADD(s1,a1); F4ADD(s2,a2); F4ADD(s3,a3);
        F4ADD(s4,a4); F4ADD(s5,a5); F4ADD(s6,a6); F4ADD(s7,a7);
        F4SQA(q0,a0); F4SQA(q1,a1); F4SQA(q2,a2); F4SQA(q3,a3);
        F4SQA(q4,a4); F4SQA(q5,a5); F4SQA(q6,a6); F4SQA(q7,a7);
    }

    SHRED(s0); SHRED(s1); SHRED(s2); SHRED(s3);
    SHRED(s4); SHRED(s5); SHRED(s6); SHRED(s7);
    SHRED(q0); SHRED(q1); SHRED(q2); SHRED(q3);
    SHRED(q4); SHRED(q5); SHRED(q6); SHRED(q7);
    if (lane == 0) {
        float4* r = &sRed[warp * 16];
        r[0]=s0; r[1]=s1; r[2]=s2; r[3]=s3; r[4]=s4; r[5]=s5; r[6]=s6; r[7]=s7;
        r[8]=q0; r[9]=q1; r[10]=q2; r[11]=q3; r[12]=q4; r[13]=q5; r[14]=q6; r[15]=q7;
    }
    __syncthreads();
    if (tid < 64) {
        const float* rf = (const float*)sRed;
        float s = 0.f;
#pragma unroll
        for (int w = 0; w < 8; w++) s += rf[w * 64 + tid];
        atomicAdd(&g_stats[tid], (double)s);
    }
}

// ---------------- K2: finalize layer-0 batchnorm ----------------
__global__ void k_fin0(const float* __restrict__ a0) {
    int c = threadIdx.x;  // 32
    double m = g_stats[c] / NTOT;
    double v = g_stats[32 + c] / NTOT - m * m;
    float rstd = (float)(1.0 / sqrt(v + 1e-9));
    float al = a0[c];
    g_dice0[c] = make_float4((float)m, rstd, al, 1.0f - al);
}

// ---------------- K3: dice0(h0) @ W1 + b1; store h1 + stats ----------------
__global__ void __launch_bounds__(CH) k_h1(const float* __restrict__ W1,
                                           const float* __restrict__ b1) {
    int blk = blockIdx.x;             // 1024 blocks x 4 chunks
    int tid = threadIdx.x;
    int lane = tid & 31, warp = tid >> 5;

    __shared__ float4 sW1[C0 * 4];    // [d<32][c4<4]
    __shared__ float4 sB1[4];
    __shared__ float4 sD0[C0];
    __shared__ float4 sRed[8 * 8];    // per-warp: 4 s + 4 q float4s

    for (int i = tid; i < C0 * 4; i += CH) sW1[i] = ((const float4*)W1)[i];
    if (tid < 4)  sB1[tid] = ((const float4*)b1)[tid];
    if (tid < C0) sD0[tid] = g_dice0[tid];
    __syncthreads();

    float4 s0=F4Z,s1=F4Z,s2=F4Z,s3=F4Z;
    float4 q0=F4Z,q1=F4Z,q2=F4Z,q3=F4Z;

    for (int lc = 0; lc < 4; lc++) {
        size_t chunk = (size_t)blk * 4 + lc;
        const float4* srcb = &g_h0[chunk * 8 * CH];

        float4 a0=sB1[0],a1=sB1[1],a2=sB1[2],a3=sB1[3];
#pragma unroll
        for (int g = 0; g < 8; g++) {
            float4 x4 = srcb[g * CH + tid];
            {
                int d = g*4+0; float hd = dice_f(x4.x, sD0[d]);
                F4FMA(a0,sW1[d*4+0],hd); F4FMA(a1,sW1[d*4+1],hd);
                F4FMA(a2,sW1[d*4+2],hd); F4FMA(a3,sW1[d*4+3],hd);
            }
            {
                int d = g*4+1; float hd = dice_f(x4.y, sD0[d]);
                F4FMA(a0,sW1[d*4+0],hd); F4FMA(a1,sW1[d*4+1],hd);
                F4FMA(a2,sW1[d*4+2],hd); F4FMA(a3,sW1[d*4+3],hd);
            }
            {
                int d = g*4+2; float hd = dice_f(x4.z, sD0[d]);
                F4FMA(a0,sW1[d*4+0],hd); F4FMA(a1,sW1[d*4+1],hd);
                F4FMA(a2,sW1[d*4+2],hd); F4FMA(a3,sW1[d*4+3],hd);
            }
            {
                int d = g*4+3; float hd = dice_f(x4.w, sD0[d]);
                F4FMA(a0,sW1[d*4+0],hd); F4FMA(a1,sW1[d*4+1],hd);
                F4FMA(a2,sW1[d*4+2],hd); F4FMA(a3,sW1[d*4+3],hd);
            }
        }
        float4* dst = &g_h1[chunk * 4 * CH];
        dst[0*CH+tid]=a0; dst[1*CH+tid]=a1; dst[2*CH+tid]=a2; dst[3*CH+tid]=a3;

        F4ADD(s0,a0); F4ADD(s1,a1); F4ADD(s2,a2); F4ADD(s3,a3);
        F4SQA(q0,a0); F4SQA(q1,a1); F4SQA(q2,a2); F4SQA(q3,a3);
    }

    SHRED(s0); SHRED(s1); SHRED(s2); SHRED(s3);
    SHRED(q0); SHRED(q1); SHRED(q2); SHRED(q3);
    if (lane == 0) {
        float4* r = &sRed[warp * 8];
        r[0]=s0; r[1]=s1; r[2]=s2; r[3]=s3;
        r[4]=q0; r[5]=q1; r[6]=q2; r[7]=q3;
    }
    __syncthreads();
    if (tid < 32) {
        const float* rf = (const float*)sRed;
        float s = 0.f;
#pragma unroll
        for (int w = 0; w < 8; w++) s += rf[w * 32 + tid];
        atomicAdd(&g_stats[64 + tid], (double)s);
    }
}

// ---------------- K4: finalize layer-1 batchnorm ----------------
__global__ void k_fin1(const float* __restrict__ a1) {
    int c = threadIdx.x;  // 16
    double m = g_stats[64 + c] / NTOT;
    double v = g_stats[80 + c] / NTOT - m * m;
    float rstd = (float)(1.0 / sqrt(v + 1e-9));
    float al = a1[c];
    g_dice1[c] = make_float4((float)m, rstd, al, 1.0f - al);
}

// ---------------- K5: score = dice1(h1)@wk + bk; out[b] += score * keys ----------------
__global__ void __launch_bounds__(CH) k_out(const float* __restrict__ keys,
                                            const float* __restrict__ wk,
                                            const float* __restrict__ bk,
                                            float* __restrict__ out) {
    int blk = blockIdx.x;             // 1024: 2 blocks per batch
    int b   = blk >> 1;
    int ck0 = (blk & 1) * 4;
    int tid = threadIdx.x;
    int lane = tid & 31, warp = tid >> 5;

    __shared__ float  sK[CH * 21];
    __shared__ float4 sD1[C1];
    __shared__ float4 sWk4[4];
    __shared__ float  sBk;
    __shared__ float4 sRed[8 * 5];

    if (tid < C1) sD1[tid] = g_dice1[tid];
    if (tid < 4)  sWk4[tid] = ((const float4*)wk)[tid];
    if (tid == 0) sBk = bk[0];

    float4 A0=F4Z,A1=F4Z,A2=F4Z,A3=F4Z,A4=F4Z;

    for (int lc = 0; lc < 4; lc++) {
        size_t chunk = (size_t)b * 8 + ck0 + lc;
        __syncthreads();
        stage_keys(sK, keys, chunk, tid);
        __syncthreads();

        const float4* hb = &g_h1[chunk * 4 * CH];
        float score = sBk;
#pragma unroll
        for (int g = 0; g < 4; g++) {
            float4 y4 = hb[g * CH + tid];
            float4 w4 = sWk4[g];
            score = fmaf(dice_f(y4.x, sD1[g*4+0]), w4.x, score);
            score = fmaf(dice_f(y4.y, sD1[g*4+1]), w4.y, score);
            score = fmaf(dice_f(y4.z, sD1[g*4+2]), w4.z, score);
            score = fmaf(dice_f(y4.w, sD1[g*4+3]), w4.w, score);
        }

        const float* kr = &sK[tid * 21];
        A0.x=fmaf(score,kr[0],A0.x);  A0.y=fmaf(score,kr[1],A0.y);
        A0.z=fmaf(score,kr[2],A0.z);  A0.w=fmaf(score,kr[3],A0.w);
        A1.x=fmaf(score,kr[4],A1.x);  A1.y=fmaf(score,kr[5],A1.y);
        A1.z=fmaf(score,kr[6],A1.z);  A1.w=fmaf(score,kr[7],A1.w);
        A2.x=fmaf(score,kr[8],A2.x);  A2.y=fmaf(score,kr[9],A2.y);
        A2.z=fmaf(score,kr[10],A2.z); A2.w=fmaf(score,kr[11],A2.w);
        A3.x=fmaf(score,kr[12],A3.x); A3.y=fmaf(score,kr[13],A3.y);
        A3.z=fmaf(score,kr[14],A3.z); A3.w=fmaf(score,kr[15],A3.w);
        A4.x=fmaf(score,kr[16],A4.x); A4.y=fmaf(score,kr[17],A4.y);
        A4.z=fmaf(score,kr[18],A4.z); A4.w=fmaf(score,kr[19],A4.w);
    }

    SHRED(A0); SHRED(A1); SHRED(A2); SHRED(A3); SHRED(A4);
    if (lane == 0) {
        float4* r = &sRed[warp * 5];
        r[0]=A0; r[1]=A1; r[2]=A2; r[3]=A3; r[4]=A4;
    }
    __syncthreads();
    if (tid < DD) {
        const float* rf = (const float*)sRed;
        float s = 0.f;
#pragma unroll
        for (int w = 0; w < 8; w++) s += rf[w * 20 + tid];
        atomicAdd(&out[b * DD + tid], s);
    }
}

// ---------------- launch ----------------
extern "C" void kernel_launch(void* const* d_in, const int* in_sizes, int n_in,
                              void* d_out, int out_size) {
    const float* keys = (const float*)d_in[0];
    const float* q    = (const float*)d_in[1];
    /* d_in[2] = mask: dead in the reference (unmasked scores are used) */
    const float* W0   = (const float*)d_in[3];
    const float* b0   = (const float*)d_in[4];
    const float* a0   = (const float*)d_in[5];
    const float* W1   = (const float*)d_in[6];
    const float* b1   = (const float*)d_in[7];
    const float* a1   = (const float*)d_in[8];
    const float* wk   = (const float*)d_in[9];
    const float* bk   = (const float*)d_in[10];
    float* out = (float*)d_out;

    k_prep<<<BB, 32>>>(q, W0, b0, out);
    k_h0  <<<1024, CH>>>(keys);
    k_fin0<<<1, 32>>>(a0);
    k_h1  <<<1024, CH>>>(W1, b1);
    k_fin1<<<1, 16>>>(a1);
    k_out <<<1024, CH>>>(keys, wk, bk, out);
}

// round 4
// speedup vs baseline: 3.8898x; 3.5575x over previous
#include <cuda_runtime.h>
#include <math.h>
#include <stdint.h>

#define BB 512
#define TT 2048
#define DD 20
#define C0 32
#define C1 16
#define CH 256
#define NCHUNK ((BB*TT)/CH)     /* 4096 */
#define NTOT   ((double)(BB)*(double)(TT))

// ---------------- scratch (device globals; no allocation) ----------------
// layout: [chunk][warp<8][g][lane<32]  -> per-warp 4KB (h0) / 2KB (h1) contiguous
__device__ float4 g_h0[(size_t)NCHUNK * 8 * CH];
__device__ float4 g_h1[(size_t)NCHUNK * 4 * CH];
__device__ float  g_Weff[BB * DD * C0];            // [b][d][c]
__device__ float  g_Cb[BB * C0];                   // [b][c]
__device__ double g_stats[96];                     // [0:32) s0 [32:64) q0 [64:80) s1 [80:96) q1
__device__ float4 g_dice0[C0];                     // {mean, rstd, alpha, 1-alpha}
__device__ float4 g_dice1[C1];

#define F4Z make_float4(0.f,0.f,0.f,0.f)
// NOTE: macro params must not collide with float4 member names (x/y/z/w)!
#define F4FMA(acc_,wv_,kk_) {acc_.x=fmaf((kk_),(wv_).x,acc_.x);acc_.y=fmaf((kk_),(wv_).y,acc_.y);acc_.z=fmaf((kk_),(wv_).z,acc_.z);acc_.w=fmaf((kk_),(wv_).w,acc_.w);}
#define F4ADD(acc_,bv_)     {acc_.x+=(bv_).x;acc_.y+=(bv_).y;acc_.z+=(bv_).z;acc_.w+=(bv_).w;}
#define F4SQA(acc_,bv_)     {acc_.x=fmaf((bv_).x,(bv_).x,acc_.x);acc_.y=fmaf((bv_).y,(bv_).y,acc_.y);acc_.z=fmaf((bv_).z,(bv_).z,acc_.z);acc_.w=fmaf((bv_).w,(bv_).w,acc_.w);}
#define SHRED(vv_)          {for(int o_=16;o_>0;o_>>=1){vv_.x+=__shfl_xor_sync(0xffffffffu,vv_.x,o_);vv_.y+=__shfl_xor_sync(0xffffffffu,vv_.y,o_);vv_.z+=__shfl_xor_sync(0xffffffffu,vv_.z,o_);vv_.w+=__shfl_xor_sync(0xffffffffu,vv_.w,o_);}}

__device__ __forceinline__ float dice_f(float x, float4 pr) {
    float xn = (x - pr.x) * pr.y;
    float p  = 1.0f / (1.0f + __expf(-xn));
    return x * (pr.z + p * pr.w);
}

// stage one 256x20 key chunk into padded smem (row stride 21 -> conflict-free)
__device__ __forceinline__ void stage_keys(float* sK, const float* __restrict__ keys,
                                           size_t chunk, int tid) {
    const float4* src = (const float4*)(keys + chunk * (size_t)(CH * DD));
#pragma unroll
    for (int i = 0; i < 5; i++) {
        float4 t = src[tid + i * CH];
        int f = tid + i * CH;
        int r = f / 5;
        int c = (f - r * 5) * 4;
        float* p = &sK[r * 21 + c];
        p[0] = t.x; p[1] = t.y; p[2] = t.z; p[3] = t.w;
    }
}

// ---------------- K0: per-batch folded weights + zero accumulators ----------------
__global__ void k_prep(const float* __restrict__ q, const float* __restrict__ W0,
                       const float* __restrict__ b0, float* __restrict__ out) {
    int b = blockIdx.x;
    int c = threadIdx.x;              // 32 threads
    if (b == 0) {
        for (int i = c; i < 96; i += 32) g_stats[i] = 0.0;
    }
    int gid = b * 32 + c;
    if (gid < BB * DD) out[gid] = 0.0f;

    float acc = b0[c];
#pragma unroll
    for (int d = 0; d < DD; d++) {
        float qd = q[b * DD + d];
        float wA = W0[(d)          * C0 + c];
        float wB = W0[(DD + d)     * C0 + c];
        float wC = W0[(2 * DD + d) * C0 + c];
        float wD = W0[(3 * DD + d) * C0 + c];
        g_Weff[(b * DD + d) * C0 + c] = wB - wC + qd * wD;
        acc += qd * (wA + wC);
    }
    g_Cb[b * C0 + c] = acc;
}

// ---------------- K1: h0 = keys @ Weff[b] + Cb[b]; store + stats ----------------
__global__ void __launch_bounds__(CH, 2) k_h0(const float* __restrict__ keys) {
    int blk = blockIdx.x;             // 1024 blocks: 2 per batch, 4 chunks each
    int b   = blk >> 1;
    int ck0 = (blk & 1) * 4;
    int tid = threadIdx.x;
    int lane = tid & 31, warp = tid >> 5;

    __shared__ float4 sW[DD * 8];     // Weff [d][c4]
    __shared__ float4 sC[8];
    __shared__ float  sK[CH * 21];    // padded key tile
    __shared__ float4 sRed[8 * 16];   // per-warp: 8 s + 8 q float4s

    for (int i = tid; i < DD * 8; i += CH)
        sW[i] = ((const float4*)(&g_Weff[b * DD * C0]))[i];
    if (tid < 8)
        sC[tid] = ((const float4*)(&g_Cb[b * C0]))[tid];

    float4 s0=F4Z,s1=F4Z,s2=F4Z,s3=F4Z,s4=F4Z,s5=F4Z,s6=F4Z,s7=F4Z;
    float4 q0=F4Z,q1=F4Z,q2=F4Z,q3=F4Z,q4=F4Z,q5=F4Z,q6=F4Z,q7=F4Z;

    for (int lc = 0; lc < 4; lc++) {
        size_t chunk = (size_t)b * 8 + ck0 + lc;
        __syncthreads();
        stage_keys(sK, keys, chunk, tid);
        __syncthreads();

        float4 a0=sC[0],a1=sC[1],a2=sC[2],a3=sC[3],a4=sC[4],a5=sC[5],a6=sC[6],a7=sC[7];
#pragma unroll
        for (int d = 0; d < DD; d++) {
            float kd = sK[tid * 21 + d];
            F4FMA(a0, sW[d*8+0], kd); F4FMA(a1, sW[d*8+1], kd);
            F4FMA(a2, sW[d*8+2], kd); F4FMA(a3, sW[d*8+3], kd);
            F4FMA(a4, sW[d*8+4], kd); F4FMA(a5, sW[d*8+5], kd);
            F4FMA(a6, sW[d*8+6], kd); F4FMA(a7, sW[d*8+7], kd);
        }
        // per-warp contiguous 4KB run: [chunk][warp][g<8][lane]
        float4* dst = &g_h0[chunk * 2048 + warp * 256];
        __stcs(&dst[0*32+lane], a0); __stcs(&dst[1*32+lane], a1);
        __stcs(&dst[2*32+lane], a2); __stcs(&dst[3*32+lane], a3);
        __stcs(&dst[4*32+lane], a4); __stcs(&dst[5*32+lane], a5);
        __stcs(&dst[6*32+lane], a6); __stcs(&dst[7*32+lane], a7);

        F4ADD(s0,a0); F4ADD(s1,a1); F4ADD(s2,a2); F4ADD(s3,a3);
        F4ADD(s4,a4); F4ADD(s5,a5); F4ADD(s6,a6); F4ADD(s7,a7);
        F4SQA(q0,a0); F4SQA(q1,a1); F4SQA(q2,a2); F4SQA(q3,a3);
        F4SQA(q4,a4); F4SQA(q5,a5); F4SQA(q6,a6); F4SQA(q7,a7);
    }

    SHRED(s0); SHRED(s1); SHRED(s2); SHRED(s3);
    SHRED(s4); SHRED(s5); SHRED(s6); SHRED(s7);
    SHRED(q0); SHRED(q1); SHRED(q2); SHRED(q3);
    SHRED(q4); SHRED(q5); SHRED(q6); SHRED(q7);
    if (lane == 0) {
        float4* r = &sRed[warp * 16];
        r[0]=s0; r[1]=s1; r[2]=s2; r[3]=s3; r[4]=s4; r[5]=s5; r[6]=s6; r[7]=s7;
        r[8]=q0; r[9]=q1; r[10]=q2; r[11]=q3; r[12]=q4; r[13]=q5; r[14]=q6; r[15]=q7;
    }
    __syncthreads();
    if (tid < 64) {
        const float* rf = (const float*)sRed;
        float s = 0.f;
#pragma unroll
        for (int w = 0; w < 8; w++) s += rf[w * 64 + tid];
        atomicAdd(&g_stats[tid], (double)s);
    }
}

// ---------------- K2: finalize layer-0 batchnorm ----------------
__global__ void k_fin0(const float* __restrict__ a0) {
    int c = threadIdx.x;  // 32
    double m = g_stats[c] / NTOT;
    double v = g_stats[32 + c] / NTOT - m * m;
    float rstd = (float)(1.0 / sqrt(v + 1e-9));
    float al = a0[c];
    g_dice0[c] = make_float4((float)m, rstd, al, 1.0f - al);
}

// ---------------- K3: dice0(h0) @ W1 + b1; store h1 + stats ----------------
#define H1STEP(xs_, d_) { float hd_ = dice_f((xs_), sD0[(d_)]); \
    F4FMA(a0,sW1[(d_)*4+0],hd_); F4FMA(a1,sW1[(d_)*4+1],hd_); \
    F4FMA(a2,sW1[(d_)*4+2],hd_); F4FMA(a3,sW1[(d_)*4+3],hd_); }

__global__ void __launch_bounds__(CH) k_h1(const float* __restrict__ W1,
                                           const float* __restrict__ b1) {
    int blk = blockIdx.x;             // 1024 blocks x 4 chunks
    int tid = threadIdx.x;
    int lane = tid & 31, warp = tid >> 5;

    __shared__ float4 sW1[C0 * 4];    // [d<32][c4<4]
    __shared__ float4 sB1[4];
    __shared__ float4 sD0[C0];
    __shared__ float4 sRed[8 * 8];    // per-warp: 4 s + 4 q float4s

    for (int i = tid; i < C0 * 4; i += CH) sW1[i] = ((const float4*)W1)[i];
    if (tid < 4)  sB1[tid] = ((const float4*)b1)[tid];
    if (tid < C0) sD0[tid] = g_dice0[tid];
    __syncthreads();

    float4 s0=F4Z,s1=F4Z,s2=F4Z,s3=F4Z;
    float4 q0=F4Z,q1=F4Z,q2=F4Z,q3=F4Z;

    for (int lc = 0; lc < 4; lc++) {
        size_t chunk = (size_t)blk * 4 + lc;
        // per-warp contiguous 4KB run: [chunk][warp][g<8][lane]
        const float4* srcb = &g_h0[chunk * 2048 + warp * 256];

        float4 a0=sB1[0],a1=sB1[1],a2=sB1[2],a3=sB1[3];

        // first half: 4 loads up front (MLP=4), then compute
        float4 xA = __ldcs(&srcb[0*32+lane]);
        float4 xB = __ldcs(&srcb[1*32+lane]);
        float4 xC = __ldcs(&srcb[2*32+lane]);
        float4 xD = __ldcs(&srcb[3*32+lane]);
        H1STEP(xA.x, 0)  H1STEP(xA.y, 1)  H1STEP(xA.z, 2)  H1STEP(xA.w, 3)
        H1STEP(xB.x, 4)  H1STEP(xB.y, 5)  H1STEP(xB.z, 6)  H1STEP(xB.w, 7)
        H1STEP(xC.x, 8)  H1STEP(xC.y, 9)  H1STEP(xC.z,10)  H1STEP(xC.w,11)
        H1STEP(xD.x,12)  H1STEP(xD.y,13)  H1STEP(xD.z,14)  H1STEP(xD.w,15)

        // second half
        xA = __ldcs(&srcb[4*32+lane]);
        xB = __ldcs(&srcb[5*32+lane]);
        xC = __ldcs(&srcb[6*32+lane]);
        xD = __ldcs(&srcb[7*32+lane]);
        H1STEP(xA.x,16)  H1STEP(xA.y,17)  H1STEP(xA.z,18)  H1STEP(xA.w,19)
        H1STEP(xB.x,20)  H1STEP(xB.y,21)  H1STEP(xB.z,22)  H1STEP(xB.w,23)
        H1STEP(xC.x,24)  H1STEP(xC.y,25)  H1STEP(xC.z,26)  H1STEP(xC.w,27)
        H1STEP(xD.x,28)  H1STEP(xD.y,29)  H1STEP(xD.z,30)  H1STEP(xD.w,31)

        // per-warp contiguous 2KB run: [chunk][warp][g<4][lane]
        float4* dst = &g_h1[chunk * 1024 + warp * 128];
        __stcs(&dst[0*32+lane], a0); __stcs(&dst[1*32+lane], a1);
        __stcs(&dst[2*32+lane], a2); __stcs(&dst[3*32+lane], a3);

        F4ADD(s0,a0); F4ADD(s1,a1); F4ADD(s2,a2); F4ADD(s3,a3);
        F4SQA(q0,a0); F4SQA(q1,a1); F4SQA(q2,a2); F4SQA(q3,a3);
    }

    SHRED(s0); SHRED(s1); SHRED(s2); SHRED(s3);
    SHRED(q0); SHRED(q1); SHRED(q2); SHRED(q3);
    if (lane == 0) {
        float4* r = &sRed[warp * 8];
        r[0]=s0; r[1]=s1; r[2]=s2; r[3]=s3;
        r[4]=q0; r[5]=q1; r[6]=q2; r[7]=q3;
    }
    __syncthreads();
    if (tid < 32) {
        const float* rf = (const float*)sRed;
        float s = 0.f;
#pragma unroll
        for (int w = 0; w < 8; w++) s += rf[w * 32 + tid];
        atomicAdd(&g_stats[64 + tid], (double)s);
    }
}

// ---------------- K4: finalize layer-1 batchnorm ----------------
__global__ void k_fin1(const float* __restrict__ a1) {
    int c = threadIdx.x;  // 16
    double m = g_stats[64 + c] / NTOT;
    double v = g_stats[80 + c] / NTOT - m * m;
    float rstd = (float)(1.0 / sqrt(v + 1e-9));
    float al = a1[c];
    g_dice1[c] = make_float4((float)m, rstd, al, 1.0f - al);
}

// ---------------- K5: score = dice1(h1)@wk + bk; out[b] += score * keys ----------------
__global__ void __launch_bounds__(CH) k_out(const float* __restrict__ keys,
                                            const float* __restrict__ wk,
                                            const float* __restrict__ bk,
                                            float* __restrict__ out) {
    int blk = blockIdx.x;             // 1024: 2 blocks per batch
    int b   = blk >> 1;
    int ck0 = (blk & 1) * 4;
    int tid = threadIdx.x;
    int lane = tid & 31, warp = tid >> 5;

    __shared__ float  sK[CH * 21];
    __shared__ float4 sD1[C1];
    __shared__ float4 sWk4[4];
    __shared__ float  sBk;
    __shared__ float4 sRed[8 * 5];

    if (tid < C1) sD1[tid] = g_dice1[tid];
    if (tid < 4)  sWk4[tid] = ((const float4*)wk)[tid];
    if (tid == 0) sBk = bk[0];

    float4 A0=F4Z,A1=F4Z,A2=F4Z,A3=F4Z,A4=F4Z;

    for (int lc = 0; lc < 4; lc++) {
        size_t chunk = (size_t)b * 8 + ck0 + lc;
        __syncthreads();
        stage_keys(sK, keys, chunk, tid);
        __syncthreads();

        // per-warp contiguous 2KB run: [chunk][warp][g<4][lane]
        const float4* hb = &g_h1[chunk * 1024 + warp * 128];
        float4 y0 = __ldcs(&hb[0*32+lane]);
        float4 y1 = __ldcs(&hb[1*32+lane]);
        float4 y2 = __ldcs(&hb[2*32+lane]);
        float4 y3 = __ldcs(&hb[3*32+lane]);

        float score = sBk;
        score = fmaf(dice_f(y0.x, sD1[ 0]), sWk4[0].x, score);
        score = fmaf(dice_f(y0.y, sD1[ 1]), sWk4[0].y, score);
        score = fmaf(dice_f(y0.z, sD1[ 2]), sWk4[0].z, score);
        score = fmaf(dice_f(y0.w, sD1[ 3]), sWk4[0].w, score);
        score = fmaf(dice_f(y1.x, sD1[ 4]), sWk4[1].x, score);
        score = fmaf(dice_f(y1.y, sD1[ 5]), sWk4[1].y, score);
        score = fmaf(dice_f(y1.z, sD1[ 6]), sWk4[1].z, score);
        score = fmaf(dice_f(y1.w, sD1[ 7]), sWk4[1].w, score);
        score = fmaf(dice_f(y2.x, sD1[ 8]), sWk4[2].x, score);
        score = fmaf(dice_f(y2.y, sD1[ 9]), sWk4[2].y, score);
        score = fmaf(dice_f(y2.z, sD1[10]), sWk4[2].z, score);
        score = fmaf(dice_f(y2.w, sD1[11]), sWk4[2].w, score);
        score = fmaf(dice_f(y3.x, sD1[12]), sWk4[3].x, score);
        score = fmaf(dice_f(y3.y, sD1[13]), sWk4[3].y, score);
        score = fmaf(dice_f(y3.z, sD1[14]), sWk4[3].z, score);
        score = fmaf(dice_f(y3.w, sD1[15]), sWk4[3].w, score);

        const float* kr = &sK[tid * 21];
        A0.x=fmaf(score,kr[0],A0.x);  A0.y=fmaf(score,kr[1],A0.y);
        A0.z=fmaf(score,kr[2],A0.z);  A0.w=fmaf(score,kr[3],A0.w);
        A1.x=fmaf(score,kr[4],A1.x);  A1.y=fmaf(score,kr[5],A1.y);
        A1.z=fmaf(score,kr[6],A1.z);  A1.w=fmaf(score,kr[7],A1.w);
        A2.x=fmaf(score,kr[8],A2.x);  A2.y=fmaf(score,kr[9],A2.y);
        A2.z=fmaf(score,kr[10],A2.z); A2.w=fmaf(score,kr[11],A2.w);
        A3.x=fmaf(score,kr[12],A3.x); A3.y=fmaf(score,kr[13],A3.y);
        A3.z=fmaf(score,kr[14],A3.z); A3.w=fmaf(score,kr[15],A3.w);
        A4.x=fmaf(score,kr[16],A4.x); A4.y=fmaf(score,kr[17],A4.y);
        A4.z=fmaf(score,kr[18],A4.z); A4.w=fmaf(score,kr[19],A4.w);
    }

    SHRED(A0); SHRED(A1); SHRED(A2); SHRED(A3); SHRED(A4);
    if (lane == 0) {
        float4* r = &sRed[warp * 5];
        r[0]=A0; r[1]=A1; r[2]=A2; r[3]=A3; r[4]=A4;
    }
    __syncthreads();
    if (tid < DD) {
        const float* rf = (const float*)sRed;
        float s = 0.f;
#pragma unroll
        for (int w = 0; w < 8; w++) s += rf[w * 20 + tid];
        atomicAdd(&out[b * DD + tid], s);
    }
}

// ---------------- launch ----------------
extern "C" void kernel_launch(void* const* d_in, const int* in_sizes, int n_in,
                              void* d_out, int out_size) {
    const float* keys = (const float*)d_in[0];
    const float* q    = (const float*)d_in[1];
    /* d_in[2] = mask: dead in the reference (unmasked scores are used) */
    const float* W0   = (const float*)d_in[3];
    const float* b0   = (const float*)d_in[4];
    const float* a0   = (const float*)d_in[5];
    const float* W1   = (const float*)d_in[6];
    const float* b1   = (const float*)d_in[7];
    const float* a1   = (const float*)d_in[8];
    const float* wk   = (const float*)d_in[9];
    const float* bk   = (const float*)d_in[10];
    float* out = (float*)d_out;

    k_prep<<<BB, 32>>>(q, W0, b0, out);
    k_h0  <<<1024, CH>>>(keys);
    k_fin0<<<1, 32>>>(a0);
    k_h1  <<<1024, CH>>>(W1, b1);
    k_fin1<<<1, 16>>>(a1);
    k_out <<<1024, CH>>>(keys, wk, bk, out);
}

// round 5
// speedup vs baseline: 4.1775x; 1.0740x over previous
#include <cuda_runtime.h>
#include <cuda_fp16.h>
#include <math.h>
#include <stdint.h>

#define BB 512
#define TT 2048
#define DD 20
#define C0 32
#define C1 16
#define CH 256
#define NCHUNK ((BB*TT)/CH)     /* 4096 */
#define NTOT   ((double)(BB)*(double)(TT))

// ---------------- scratch (device globals; no allocation) ----------------
// fp16 storage. h0: [chunk][warp<8][g<4][lane<32] uint4 (8 halfs) = 67MB
//               h1: [chunk][warp<8][g<2][lane<32] uint4           = 33.5MB
__device__ uint4  g_h0h[(size_t)NCHUNK * 8 * 4 * 32];
__device__ uint4  g_h1h[(size_t)NCHUNK * 8 * 2 * 32];
__device__ float  g_Weff[BB * DD * C0];            // [b][d][c]
__device__ float  g_Cb[BB * C0];                   // [b][c]
__device__ double g_stats[96];                     // [0:32) s0 [32:64) q0 [64:80) s1 [80:96) q1
__device__ float4 g_dice0[C0];                     // {mean, rstd, alpha, 1-alpha}
__device__ float4 g_dice1[C1];

#define F4Z make_float4(0.f,0.f,0.f,0.f)
// NOTE: macro params must not collide with float4 member names (x/y/z/w)!
#define F4FMA(acc_,wv_,kk_) {acc_.x=fmaf((kk_),(wv_).x,acc_.x);acc_.y=fmaf((kk_),(wv_).y,acc_.y);acc_.z=fmaf((kk_),(wv_).z,acc_.z);acc_.w=fmaf((kk_),(wv_).w,acc_.w);}
#define F4ADD(acc_,bv_)     {acc_.x+=(bv_).x;acc_.y+=(bv_).y;acc_.z+=(bv_).z;acc_.w+=(bv_).w;}
#define F4SQA(acc_,bv_)     {acc_.x=fmaf((bv_).x,(bv_).x,acc_.x);acc_.y=fmaf((bv_).y,(bv_).y,acc_.y);acc_.z=fmaf((bv_).z,(bv_).z,acc_.z);acc_.w=fmaf((bv_).w,(bv_).w,acc_.w);}
#define SHRED(vv_)          {for(int o_=16;o_>0;o_>>=1){vv_.x+=__shfl_xor_sync(0xffffffffu,vv_.x,o_);vv_.y+=__shfl_xor_sync(0xffffffffu,vv_.y,o_);vv_.z+=__shfl_xor_sync(0xffffffffu,vv_.z,o_);vv_.w+=__shfl_xor_sync(0xffffffffu,vv_.w,o_);}}

__device__ __forceinline__ uint32_t pk2(float a, float b) {
    union { __half2 h; uint32_t u; } cv;
    cv.h = __floats2half2_rn(a, b);
    return cv.u;
}
__device__ __forceinline__ float2 upk2(uint32_t u) {
    union { __half2 h; uint32_t u; } cv;
    cv.u = u;
    return __half22float2(cv.h);
}

__device__ __forceinline__ float dice_f(float x, float4 pr) {
    float xn = (x - pr.x) * pr.y;
    float p  = 1.0f / (1.0f + __expf(-xn));
    return x * (pr.z + p * pr.w);
}

// stage one 256x20 key chunk into padded smem (row stride 21 -> conflict-free)
__device__ __forceinline__ void stage_keys(float* sK, const float* __restrict__ keys,
                                           size_t chunk, int tid) {
    const float4* src = (const float4*)(keys + chunk * (size_t)(CH * DD));
#pragma unroll
    for (int i = 0; i < 5; i++) {
        float4 t = src[tid + i * CH];
        int f = tid + i * CH;
        int r = f / 5;
        int c = (f - r * 5) * 4;
        float* p = &sK[r * 21 + c];
        p[0] = t.x; p[1] = t.y; p[2] = t.z; p[3] = t.w;
    }
}

// ---------------- K0: per-batch folded weights + zero accumulators ----------------
__global__ void k_prep(const float* __restrict__ q, const float* __restrict__ W0,
                       const float* __restrict__ b0, float* __restrict__ out) {
    int b = blockIdx.x;
    int c = threadIdx.x;              // 32 threads
    if (b == 0) {
        for (int i = c; i < 96; i += 32) g_stats[i] = 0.0;
    }
    int gid = b * 32 + c;
    if (gid < BB * DD) out[gid] = 0.0f;

    float acc = b0[c];
#pragma unroll
    for (int d = 0; d < DD; d++) {
        float qd = q[b * DD + d];
        float wA = W0[(d)          * C0 + c];
        float wB = W0[(DD + d)     * C0 + c];
        float wC = W0[(2 * DD + d) * C0 + c];
        float wD = W0[(3 * DD + d) * C0 + c];
        g_Weff[(b * DD + d) * C0 + c] = wB - wC + qd * wD;
        acc += qd * (wA + wC);
    }
    g_Cb[b * C0 + c] = acc;
}

// ---------------- K1: h0 = keys @ Weff[b] + Cb[b]; store fp16 + stats ----------------
__global__ void __launch_bounds__(CH, 2) k_h0(const float* __restrict__ keys) {
    int blk = blockIdx.x;             // 1024 blocks: 2 per batch, 4 chunks each
    int b   = blk >> 1;
    int ck0 = (blk & 1) * 4;
    int tid = threadIdx.x;
    int lane = tid & 31, warp = tid >> 5;

    __shared__ float4 sW[DD * 8];     // Weff [d][c4]
    __shared__ float4 sC[8];
    __shared__ float  sK[CH * 21];    // padded key tile
    __shared__ float4 sRed[8 * 16];   // per-warp: 8 s + 8 q float4s

    for (int i = tid; i < DD * 8; i += CH)
        sW[i] = ((const float4*)(&g_Weff[b * DD * C0]))[i];
    if (tid < 8)
        sC[tid] = ((const float4*)(&g_Cb[b * C0]))[tid];

    float4 s0=F4Z,s1=F4Z,s2=F4Z,s3=F4Z,s4=F4Z,s5=F4Z,s6=F4Z,s7=F4Z;
    float4 q0=F4Z,q1=F4Z,q2=F4Z,q3=F4Z,q4=F4Z,q5=F4Z,q6=F4Z,q7=F4Z;

    for (int lc = 0; lc < 4; lc++) {
        size_t chunk = (size_t)b * 8 + ck0 + lc;
        __syncthreads();
        stage_keys(sK, keys, chunk, tid);
        __syncthreads();

        float4 a0=sC[0],a1=sC[1],a2=sC[2],a3=sC[3],a4=sC[4],a5=sC[5],a6=sC[6],a7=sC[7];
#pragma unroll
        for (int d = 0; d < DD; d++) {
            float kd = sK[tid * 21 + d];
            F4FMA(a0, sW[d*8+0], kd); F4FMA(a1, sW[d*8+1], kd);
            F4FMA(a2, sW[d*8+2], kd); F4FMA(a3, sW[d*8+3], kd);
            F4FMA(a4, sW[d*8+4], kd); F4FMA(a5, sW[d*8+5], kd);
            F4FMA(a6, sW[d*8+6], kd); F4FMA(a7, sW[d*8+7], kd);
        }
        // pack to fp16: per-warp contiguous 2KB run
        uint4 p0 = make_uint4(pk2(a0.x,a0.y), pk2(a0.z,a0.w), pk2(a1.x,a1.y), pk2(a1.z,a1.w));
        uint4 p1 = make_uint4(pk2(a2.x,a2.y), pk2(a2.z,a2.w), pk2(a3.x,a3.y), pk2(a3.z,a3.w));
        uint4 p2 = make_uint4(pk2(a4.x,a4.y), pk2(a4.z,a4.w), pk2(a5.x,a5.y), pk2(a5.z,a5.w));
        uint4 p3 = make_uint4(pk2(a6.x,a6.y), pk2(a6.z,a6.w), pk2(a7.x,a7.y), pk2(a7.z,a7.w));
        uint4* dst = &g_h0h[chunk * 1024 + warp * 128];
        __stcs(&dst[0*32+lane], p0); __stcs(&dst[1*32+lane], p1);
        __stcs(&dst[2*32+lane], p2); __stcs(&dst[3*32+lane], p3);

        F4ADD(s0,a0); F4ADD(s1,a1); F4ADD(s2,a2); F4ADD(s3,a3);
        F4ADD(s4,a4); F4ADD(s5,a5); F4ADD(s6,a6); F4ADD(s7,a7);
        F4SQA(q0,a0); F4SQA(q1,a1); F4SQA(q2,a2); F4SQA(q3,a3);
        F4SQA(q4,a4); F4SQA(q5,a5); F4SQA(q6,a6); F4SQA(q7,a7);
    }

    SHRED(s0); SHRED(s1); SHRED(s2); SHRED(s3);
    SHRED(s4); SHRED(s5); SHRED(s6); SHRED(s7);
    SHRED(q0); SHRED(q1); SHRED(q2); SHRED(q3);
    SHRED(q4); SHRED(q5); SHRED(q6); SHRED(q7);
    if (lane == 0) {
        float4* r = &sRed[warp * 16];
        r[0]=s0; r[1]=s1; r[2]=s2; r[3]=s3; r[4]=s4; r[5]=s5; r[6]=s6; r[7]=s7;
        r[8]=q0; r[9]=q1; r[10]=q2; r[11]=q3; r[12]=q4; r[13]=q5; r[14]=q6; r[15]=q7;
    }
    __syncthreads();
    if (tid < 64) {
        const float* rf = (const float*)sRed;
        float s = 0.f;
#pragma unroll
        for (int w = 0; w < 8; w++) s += rf[w * 64 + tid];
        atomicAdd(&g_stats[tid], (double)s);
    }
}

// ---------------- K2: finalize layer-0 batchnorm ----------------
__global__ void k_fin0(const float* __restrict__ a0) {
    int c = threadIdx.x;  // 32
    double m = g_stats[c] / NTOT;
    double v = g_stats[32 + c] / NTOT - m * m;
    float rstd = (float)(1.0 / sqrt(v + 1e-9));
    float al = a0[c];
    g_dice0[c] = make_float4((float)m, rstd, al, 1.0f - al);
}

// ---------------- K3: dice0(h0) @ W1 + b1; store fp16 + stats ----------------
#define H1STEP(xs_, d_) { float hd_ = dice_f((xs_), sD0[(d_)]); \
    F4FMA(a0,sW1[(d_)*4+0],hd_); F4FMA(a1,sW1[(d_)*4+1],hd_); \
    F4FMA(a2,sW1[(d_)*4+2],hd_); F4FMA(a3,sW1[(d_)*4+3],hd_); }
#define H1PAIR(us_, d_) { float2 f_ = upk2(us_); H1STEP(f_.x, d_) H1STEP(f_.y, (d_)+1) }

__global__ void __launch_bounds__(CH) k_h1(const float* __restrict__ W1,
                                           const float* __restrict__ b1) {
    int blk = blockIdx.x;             // 1024 blocks x 4 chunks
    int tid = threadIdx.x;
    int lane = tid & 31, warp = tid >> 5;

    __shared__ float4 sW1[C0 * 4];    // [d<32][c4<4]
    __shared__ float4 sB1[4];
    __shared__ float4 sD0[C0];
    __shared__ float4 sRed[8 * 8];    // per-warp: 4 s + 4 q float4s

    for (int i = tid; i < C0 * 4; i += CH) sW1[i] = ((const float4*)W1)[i];
    if (tid < 4)  sB1[tid] = ((const float4*)b1)[tid];
    if (tid < C0) sD0[tid] = g_dice0[tid];
    __syncthreads();

    float4 s0=F4Z,s1=F4Z,s2=F4Z,s3=F4Z;
    float4 q0=F4Z,q1=F4Z,q2=F4Z,q3=F4Z;

    // software pipeline: prefetch chunk lc+1 while computing lc
    const uint4* sbase = &g_h0h[(size_t)blk * 4 * 1024 + warp * 128];
    uint4 nA = __ldcs(&sbase[0*32+lane]);
    uint4 nB = __ldcs(&sbase[1*32+lane]);
    uint4 nC = __ldcs(&sbase[2*32+lane]);
    uint4 nD = __ldcs(&sbase[3*32+lane]);

#pragma unroll
    for (int lc = 0; lc < 4; lc++) {
        uint4 xA = nA, xB = nB, xC = nC, xD = nD;
        if (lc < 3) {
            const uint4* np = sbase + (size_t)(lc + 1) * 1024;
            nA = __ldcs(&np[0*32+lane]);
            nB = __ldcs(&np[1*32+lane]);
            nC = __ldcs(&np[2*32+lane]);
            nD = __ldcs(&np[3*32+lane]);
        }

        float4 a0=sB1[0],a1=sB1[1],a2=sB1[2],a3=sB1[3];
        H1PAIR(xA.x, 0)  H1PAIR(xA.y, 2)  H1PAIR(xA.z, 4)  H1PAIR(xA.w, 6)
        H1PAIR(xB.x, 8)  H1PAIR(xB.y,10)  H1PAIR(xB.z,12)  H1PAIR(xB.w,14)
        H1PAIR(xC.x,16)  H1PAIR(xC.y,18)  H1PAIR(xC.z,20)  H1PAIR(xC.w,22)
        H1PAIR(xD.x,24)  H1PAIR(xD.y,26)  H1PAIR(xD.z,28)  H1PAIR(xD.w,30)

        size_t chunk = (size_t)blk * 4 + lc;
        uint4 pA = make_uint4(pk2(a0.x,a0.y), pk2(a0.z,a0.w), pk2(a1.x,a1.y), pk2(a1.z,a1.w));
        uint4 pB = make_uint4(pk2(a2.x,a2.y), pk2(a2.z,a2.w), pk2(a3.x,a3.y), pk2(a3.z,a3.w));
        uint4* dst = &g_h1h[chunk * 512 + warp * 64];
        __stcs(&dst[0*32+lane], pA); __stcs(&dst[1*32+lane], pB);

        F4ADD(s0,a0); F4ADD(s1,a1); F4ADD(s2,a2); F4ADD(s3,a3);
        F4SQA(q0,a0); F4SQA(q1,a1); F4SQA(q2,a2); F4SQA(q3,a3);
    }

    SHRED(s0); SHRED(s1); SHRED(s2); SHRED(s3);
    SHRED(q0); SHRED(q1); SHRED(q2); SHRED(q3);
    if (lane == 0) {
        float4* r = &sRed[warp * 8];
        r[0]=s0; r[1]=s1; r[2]=s2; r[3]=s3;
        r[4]=q0; r[5]=q1; r[6]=q2; r[7]=q3;
    }
    __syncthreads();
    if (tid < 32) {
        const float* rf = (const float*)sRed;
        float s = 0.f;
#pragma unroll
        for (int w = 0; w < 8; w++) s += rf[w * 32 + tid];
        atomicAdd(&g_stats[64 + tid], (double)s);
    }
}

// ---------------- K4: finalize layer-1 batchnorm ----------------
__global__ void k_fin1(const float* __restrict__ a1) {
    int c = threadIdx.x;  // 16
    double m = g_stats[64 + c] / NTOT;
    double v = g_stats[80 + c] / NTOT - m * m;
    float rstd = (float)(1.0 / sqrt(v + 1e-9));
    float al = a1[c];
    g_dice1[c] = make_float4((float)m, rstd, al, 1.0f - al);
}

// ---------------- K5: score = dice1(h1)@wk + bk; out[b] += score * keys ----------------
__global__ void __launch_bounds__(CH) k_out(const float* __restrict__ keys,
                                            const float* __restrict__ wk,
                                            const float* __restrict__ bk,
                                            float* __restrict__ out) {
    int blk = blockIdx.x;             // 1024: 2 blocks per batch
    int b   = blk >> 1;
    int ck0 = (blk & 1) * 4;
    int tid = threadIdx.x;
    int lane = tid & 31, warp = tid >> 5;

    __shared__ float  sK[CH * 21];
    __shared__ float4 sD1[C1];
    __shared__ float4 sWk4[4];
    __shared__ float  sBk;
    __shared__ float4 sRed[8 * 5];

    if (tid < C1) sD1[tid] = g_dice1[tid];
    if (tid < 4)  sWk4[tid] = ((const float4*)wk)[tid];
    if (tid == 0) sBk = bk[0];

    float4 A0=F4Z,A1=F4Z,A2=F4Z,A3=F4Z,A4=F4Z;

    for (int lc = 0; lc < 4; lc++) {
        size_t chunk = (size_t)b * 8 + ck0 + lc;
        // issue independent h1 loads BEFORE the key-staging barrier
        const uint4* hb = &g_h1h[chunk * 512 + warp * 64];
        uint4 u0 = __ldcs(&hb[0*32+lane]);
        uint4 u1 = __ldcs(&hb[1*32+lane]);

        __syncthreads();
        stage_keys(sK, keys, chunk, tid);
        __syncthreads();

        float score = sBk;
        {
            float2 f;
            f = upk2(u0.x);
            score = fmaf(dice_f(f.x, sD1[ 0]), sWk4[0].x, score);
            score = fmaf(dice_f(f.y, sD1[ 1]), sWk4[0].y, score);
            f = upk2(u0.y);
            score = fmaf(dice_f(f.x, sD1[ 2]), sWk4[0].z, score);
            score = fmaf(dice_f(f.y, sD1[ 3]), sWk4[0].w, score);
            f = upk2(u0.z);
            score = fmaf(dice_f(f.x, sD1[ 4]), sWk4[1].x, score);
            score = fmaf(dice_f(f.y, sD1[ 5]), sWk4[1].y, score);
            f = upk2(u0.w);
            score = fmaf(dice_f(f.x, sD1[ 6]), sWk4[1].z, score);
            score = fmaf(dice_f(f.y, sD1[ 7]), sWk4[1].w, score);
            f = upk2(u1.x);
            score = fmaf(dice_f(f.x, sD1[ 8]), sWk4[2].x, score);
            score = fmaf(dice_f(f.y, sD1[ 9]), sWk4[2].y, score);
            f = upk2(u1.y);
            score = fmaf(dice_f(f.x, sD1[10]), sWk4[2].z, score);
            score = fmaf(dice_f(f.y, sD1[11]), sWk4[2].w, score);
            f = upk2(u1.z);
            score = fmaf(dice_f(f.x, sD1[12]), sWk4[3].x, score);
            score = fmaf(dice_f(f.y, sD1[13]), sWk4[3].y, score);
            f = upk2(u1.w);
            score = fmaf(dice_f(f.x, sD1[14]), sWk4[3].z, score);
            score = fmaf(dice_f(f.y, sD1[15]), sWk4[3].w, score);
        }

        const float* kr = &sK[tid * 21];
        A0.x=fmaf(score,kr[0],A0.x);  A0.y=fmaf(score,kr[1],A0.y);
        A0.z=fmaf(score,kr[2],A0.z);  A0.w=fmaf(score,kr[3],A0.w);
        A1.x=fmaf(score,kr[4],A1.x);  A1.y=fmaf(score,kr[5],A1.y);
        A1.z=fmaf(score,kr[6],A1.z);  A1.w=fmaf(score,kr[7],A1.w);
        A2.x=fmaf(score,kr[8],A2.x);  A2.y=fmaf(score,kr[9],A2.y);
        A2.z=fmaf(score,kr[10],A2.z); A2.w=fmaf(score,kr[11],A2.w);
        A3.x=fmaf(score,kr[12],A3.x); A3.y=fmaf(score,kr[13],A3.y);
        A3.z=fmaf(score,kr[14],A3.z); A3.w=fmaf(score,kr[15],A3.w);
        A4.x=fmaf(score,kr[16],A4.x); A4.y=fmaf(score,kr[17],A4.y);
        A4.z=fmaf(score,kr[18],A4.z); A4.w=fmaf(score,kr[19],A4.w);
    }

    SHRED(A0); SHRED(A1); SHRED(A2); SHRED(A3); SHRED(A4);
    if (lane == 0) {
        float4* r = &sRed[warp * 5];
        r[0]=A0; r[1]=A1; r[2]=A2; r[3]=A3; r[4]=A4;
    }
    __syncthreads();
    if (tid < DD) {
        const float* rf = (const float*)sRed;
        float s = 0.f;
#pragma unroll
        for (int w = 0; w < 8; w++) s += rf[w * 20 + tid];
        atomicAdd(&out[b * DD + tid], s);
    }
}

// ---------------- launch ----------------
extern "C" void kernel_launch(void* const* d_in, const int* in_sizes, int n_in,
                              void* d_out, int out_size) {
    const float* keys = (const float*)d_in[0];
    const float* q    = (const float*)d_in[1];
    /* d_in[2] = mask: dead in the reference (unmasked scores are used) */
    const float* W0   = (const float*)d_in[3];
    const float* b0   = (const float*)d_in[4];
    const float* a0   = (const float*)d_in[5];
    const float* W1   = (const float*)d_in[6];
    const float* b1   = (const float*)d_in[7];
    const float* a1   = (const float*)d_in[8];
    const float* wk   = (const float*)d_in[9];
    const float* bk   = (const float*)d_in[10];
    float* out = (float*)d_out;

    k_prep<<<BB, 32>>>(q, W0, b0, out);
    k_h0  <<<1024, CH>>>(keys);
    k_fin0<<<1, 32>>>(a0);
    k_h1  <<<1024, CH>>>(W1, b1);
    k_fin1<<<1, 16>>>(a1);
    k_out <<<1024, CH>>>(keys, wk, bk, out);
}

// round 6
// speedup vs baseline: 4.4875x; 1.0742x over previous
#include <cuda_runtime.h>
#include <cuda_fp16.h>
#include <math.h>
#include <stdint.h>

#define BB 512
#define TT 2048
#define DD 20
#define C0 32
#define C1 16
#define CH 256
#define NCHUNK ((BB*TT)/CH)     /* 4096 */
#define NTOT   ((double)(BB)*(double)(TT))

typedef unsigned long long u64;

// ---------------- scratch (device globals; no allocation) ----------------
// fp16 storage. h0: [chunk][warp<8][g<4][lane<32] uint4 (8 halfs) = 67MB
//               h1: [chunk][warp<8][g<2][lane<32] uint4           = 33.5MB
__device__ uint4  g_h0h[(size_t)NCHUNK * 8 * 4 * 32];
__device__ uint4  g_h1h[(size_t)NCHUNK * 8 * 2 * 32];
__device__ float  g_Weff[BB * DD * C0];            // [b][d][c]
__device__ float  g_Cb[BB * C0];                   // [b][c]
__device__ double g_stats[96];                     // [0:32) s0 [32:64) q0 [64:80) s1 [80:96) q1
__device__ float4 g_dice0[C0];                     // {mean, rstd, alpha, 1-alpha}
__device__ float4 g_dice1[C1];

#define F4Z make_float4(0.f,0.f,0.f,0.f)
#define SHRED(vv_) {for(int o_=16;o_>0;o_>>=1){vv_.x+=__shfl_xor_sync(0xffffffffu,vv_.x,o_);vv_.y+=__shfl_xor_sync(0xffffffffu,vv_.y,o_);vv_.z+=__shfl_xor_sync(0xffffffffu,vv_.z,o_);vv_.w+=__shfl_xor_sync(0xffffffffu,vv_.w,o_);}}

// ---- packed f32x2 primitives (FFMA2: 2 fp32 FMA per instruction) ----
__device__ __forceinline__ u64 pack2(float lo, float hi) {
    u64 r; asm("mov.b64 %0, {%1, %2};" : "=l"(r) : "f"(lo), "f"(hi)); return r;
}
__device__ __forceinline__ void unpack2(u64 v, float& lo, float& hi) {
    asm("mov.b64 {%0, %1}, %2;" : "=f"(lo), "=f"(hi) : "l"(v));
}
__device__ __forceinline__ void fma2(u64& acc, u64 a, u64 b) {
    asm("fma.rn.f32x2 %0, %1, %2, %0;" : "+l"(acc) : "l"(a), "l"(b));
}
__device__ __forceinline__ void add2(u64& acc, u64 a) {
    asm("add.rn.f32x2 %0, %1, %0;" : "+l"(acc) : "l"(a));
}
__device__ __forceinline__ uint32_t h2p(u64 v) {   // packed f32x2 -> half2 bits
    float lo, hi; unpack2(v, lo, hi);
    union { __half2 h; uint32_t u; } cv;
    cv.h = __floats2half2_rn(lo, hi);
    return cv.u;
}
__device__ __forceinline__ float2 upkh(uint32_t u) {  // half2 bits -> float2
    union { __half2 h; uint32_t u; } cv;
    cv.u = u;
    return __half22float2(cv.h);
}

__device__ __forceinline__ float dice_f(float x, float4 pr) {
    float xn = (x - pr.x) * pr.y;
    float p  = 1.0f / (1.0f + __expf(-xn));
    return x * (pr.z + p * pr.w);
}

// stage one 256x20 key chunk into padded smem (row stride 21 -> conflict-free)
__device__ __forceinline__ void stage_keys(float* sK, const float* __restrict__ keys,
                                           size_t chunk, int tid) {
    const float4* src = (const float4*)(keys + chunk * (size_t)(CH * DD));
#pragma unroll
    for (int i = 0; i < 5; i++) {
        float4 t = src[tid + i * CH];
        int f = tid + i * CH;
        int r = f / 5;
        int c = (f - r * 5) * 4;
        float* p = &sK[r * 21 + c];
        p[0] = t.x; p[1] = t.y; p[2] = t.z; p[3] = t.w;
    }
}

// ---------------- K0: per-batch folded weights + zero accumulators ----------------
__global__ void k_prep(const float* __restrict__ q, const float* __restrict__ W0,
                       const float* __restrict__ b0, float* __restrict__ out) {
    int b = blockIdx.x;
    int c = threadIdx.x;              // 32 threads
    if (b == 0) {
        for (int i = c; i < 96; i += 32) g_stats[i] = 0.0;
    }
    int gid = b * 32 + c;
    if (gid < BB * DD) out[gid] = 0.0f;

    float acc = b0[c];
#pragma unroll
    for (int d = 0; d < DD; d++) {
        float qd = q[b * DD + d];
        float wA = W0[(d)          * C0 + c];
        float wB = W0[(DD + d)     * C0 + c];
        float wC = W0[(2 * DD + d) * C0 + c];
        float wD = W0[(3 * DD + d) * C0 + c];
        g_Weff[(b * DD + d) * C0 + c] = wB - wC + qd * wD;
        acc += qd * (wA + wC);
    }
    g_Cb[b * C0 + c] = acc;
}

// ---------------- K1: h0 = keys @ Weff[b] + Cb[b]; store fp16 + stats ----------------
__global__ void __launch_bounds__(CH, 2) k_h0(const float* __restrict__ keys) {
    int blk = blockIdx.x;             // 1024 blocks: 2 per batch, 4 chunks each
    int b   = blk >> 1;
    int ck0 = (blk & 1) * 4;
    int tid = threadIdx.x;
    int lane = tid & 31, warp = tid >> 5;

    __shared__ float4 sW[DD * 8];     // Weff [d][c4] (aliased as ulonglong2 pairs)
    __shared__ float4 sC[8];
    __shared__ float  sK[CH * 21];    // padded key tile
    __shared__ float4 sRed[8 * 16];   // per-warp: 8 s + 8 q float4s

    for (int i = tid; i < DD * 8; i += CH)
        sW[i] = ((const float4*)(&g_Weff[b * DD * C0]))[i];
    if (tid < 8)
        sC[tid] = ((const float4*)(&g_Cb[b * C0]))[tid];

    const ulonglong2* sW2 = (const ulonglong2*)sW;   // [d*8+i]: .x=pair(4i,4i+1) .y=pair(4i+2,4i+3)
    const ulonglong2* sC2 = (const ulonglong2*)sC;

    u64 s0=0,s1=0,s2=0,s3=0,s4=0,s5=0,s6=0,s7=0,s8=0,s9=0,s10=0,s11=0,s12=0,s13=0,s14=0,s15=0;
    u64 q0=0,q1=0,q2=0,q3=0,q4=0,q5=0,q6=0,q7=0,q8=0,q9=0,q10=0,q11=0,q12=0,q13=0,q14=0,q15=0;

    for (int lc = 0; lc < 4; lc++) {
        size_t chunk = (size_t)b * 8 + ck0 + lc;
        __syncthreads();
        stage_keys(sK, keys, chunk, tid);
        __syncthreads();

        u64 a0,a1,a2,a3,a4,a5,a6,a7,a8,a9,a10,a11,a12,a13,a14,a15;
        { ulonglong2 t;
          t=sC2[0]; a0 =t.x; a1 =t.y;  t=sC2[1]; a2 =t.x; a3 =t.y;
          t=sC2[2]; a4 =t.x; a5 =t.y;  t=sC2[3]; a6 =t.x; a7 =t.y;
          t=sC2[4]; a8 =t.x; a9 =t.y;  t=sC2[5]; a10=t.x; a11=t.y;
          t=sC2[6]; a12=t.x; a13=t.y;  t=sC2[7]; a14=t.x; a15=t.y; }

#pragma unroll
        for (int d = 0; d < DD; d++) {
            float kd = sK[tid * 21 + d];
            u64 kdd = pack2(kd, kd);
            ulonglong2 w;
            w=sW2[d*8+0]; fma2(a0 ,w.x,kdd); fma2(a1 ,w.y,kdd);
            w=sW2[d*8+1]; fma2(a2 ,w.x,kdd); fma2(a3 ,w.y,kdd);
            w=sW2[d*8+2]; fma2(a4 ,w.x,kdd); fma2(a5 ,w.y,kdd);
            w=sW2[d*8+3]; fma2(a6 ,w.x,kdd); fma2(a7 ,w.y,kdd);
            w=sW2[d*8+4]; fma2(a8 ,w.x,kdd); fma2(a9 ,w.y,kdd);
            w=sW2[d*8+5]; fma2(a10,w.x,kdd); fma2(a11,w.y,kdd);
            w=sW2[d*8+6]; fma2(a12,w.x,kdd); fma2(a13,w.y,kdd);
            w=sW2[d*8+7]; fma2(a14,w.x,kdd); fma2(a15,w.y,kdd);
        }
        // pack to fp16: per-warp contiguous 2KB run
        uint4 p0 = make_uint4(h2p(a0), h2p(a1), h2p(a2), h2p(a3));
        uint4 p1 = make_uint4(h2p(a4), h2p(a5), h2p(a6), h2p(a7));
        uint4 p2 = make_uint4(h2p(a8), h2p(a9), h2p(a10), h2p(a11));
        uint4 p3 = make_uint4(h2p(a12), h2p(a13), h2p(a14), h2p(a15));
        uint4* dst = &g_h0h[chunk * 1024 + warp * 128];
        __stcs(&dst[0*32+lane], p0); __stcs(&dst[1*32+lane], p1);
        __stcs(&dst[2*32+lane], p2); __stcs(&dst[3*32+lane], p3);

        add2(s0,a0); add2(s1,a1); add2(s2,a2); add2(s3,a3);
        add2(s4,a4); add2(s5,a5); add2(s6,a6); add2(s7,a7);
        add2(s8,a8); add2(s9,a9); add2(s10,a10); add2(s11,a11);
        add2(s12,a12); add2(s13,a13); add2(s14,a14); add2(s15,a15);
        fma2(q0,a0,a0); fma2(q1,a1,a1); fma2(q2,a2,a2); fma2(q3,a3,a3);
        fma2(q4,a4,a4); fma2(q5,a5,a5); fma2(q6,a6,a6); fma2(q7,a7,a7);
        fma2(q8,a8,a8); fma2(q9,a9,a9); fma2(q10,a10,a10); fma2(q11,a11,a11);
        fma2(q12,a12,a12); fma2(q13,a13,a13); fma2(q14,a14,a14); fma2(q15,a15,a15);
    }

    // unpack to float4s (channel order 0..31) and reduce
    float4 S0,S1,S2,S3,S4,S5,S6,S7, Q0,Q1,Q2,Q3,Q4,Q5,Q6,Q7;
    unpack2(s0,S0.x,S0.y); unpack2(s1,S0.z,S0.w);  unpack2(s2,S1.x,S1.y); unpack2(s3,S1.z,S1.w);
    unpack2(s4,S2.x,S2.y); unpack2(s5,S2.z,S2.w);  unpack2(s6,S3.x,S3.y); unpack2(s7,S3.z,S3.w);
    unpack2(s8,S4.x,S4.y); unpack2(s9,S4.z,S4.w);  unpack2(s10,S5.x,S5.y); unpack2(s11,S5.z,S5.w);
    unpack2(s12,S6.x,S6.y); unpack2(s13,S6.z,S6.w); unpack2(s14,S7.x,S7.y); unpack2(s15,S7.z,S7.w);
    unpack2(q0,Q0.x,Q0.y); unpack2(q1,Q0.z,Q0.w);  unpack2(q2,Q1.x,Q1.y); unpack2(q3,Q1.z,Q1.w);
    unpack2(q4,Q2.x,Q2.y); unpack2(q5,Q2.z,Q2.w);  unpack2(q6,Q3.x,Q3.y); unpack2(q7,Q3.z,Q3.w);
    unpack2(q8,Q4.x,Q4.y); unpack2(q9,Q4.z,Q4.w);  unpack2(q10,Q5.x,Q5.y); unpack2(q11,Q5.z,Q5.w);
    unpack2(q12,Q6.x,Q6.y); unpack2(q13,Q6.z,Q6.w); unpack2(q14,Q7.x,Q7.y); unpack2(q15,Q7.z,Q7.w);

    SHRED(S0); SHRED(S1); SHRED(S2); SHRED(S3);
    SHRED(S4); SHRED(S5); SHRED(S6); SHRED(S7);
    SHRED(Q0); SHRED(Q1); SHRED(Q2); SHRED(Q3);
    SHRED(Q4); SHRED(Q5); SHRED(Q6); SHRED(Q7);
    if (lane == 0) {
        float4* r = &sRed[warp * 16];
        r[0]=S0; r[1]=S1; r[2]=S2; r[3]=S3; r[4]=S4; r[5]=S5; r[6]=S6; r[7]=S7;
        r[8]=Q0; r[9]=Q1; r[10]=Q2; r[11]=Q3; r[12]=Q4; r[13]=Q5; r[14]=Q6; r[15]=Q7;
    }
    __syncthreads();
    if (tid < 64) {
        const float* rf = (const float*)sRed;
        float s = 0.f;
#pragma unroll
        for (int w = 0; w < 8; w++) s += rf[w * 64 + tid];
        atomicAdd(&g_stats[tid], (double)s);
    }
}

// ---------------- K2: finalize layer-0 batchnorm ----------------
__global__ void k_fin0(const float* __restrict__ a0) {
    int c = threadIdx.x;  // 32
    double m = g_stats[c] / NTOT;
    double v = g_stats[32 + c] / NTOT - m * m;
    float rstd = (float)(1.0 / sqrt(v + 1e-9));
    float al = a0[c];
    g_dice0[c] = make_float4((float)m, rstd, al, 1.0f - al);
}

// ---------------- K3: dice0(h0) @ W1 + b1; store fp16 + stats ----------------
#define H1STEP(xs_, d_) { float hd_ = dice_f((xs_), sD0[(d_)]); \
    u64 hdd_ = pack2(hd_, hd_); ulonglong2 w_; \
    w_=sW1_2[(d_)*4+0]; fma2(b0,w_.x,hdd_); fma2(b1,w_.y,hdd_); \
    w_=sW1_2[(d_)*4+1]; fma2(b2,w_.x,hdd_); fma2(b3,w_.y,hdd_); \
    w_=sW1_2[(d_)*4+2]; fma2(b4,w_.x,hdd_); fma2(b5,w_.y,hdd_); \
    w_=sW1_2[(d_)*4+3]; fma2(b6,w_.x,hdd_); fma2(b7,w_.y,hdd_); }
#define H1PAIR(us_, d_) { float2 f_ = upkh(us_); H1STEP(f_.x, d_) H1STEP(f_.y, (d_)+1) }

__global__ void __launch_bounds__(CH, 3) k_h1(const float* __restrict__ W1,
                                              const float* __restrict__ b1) {
    int blk = blockIdx.x;             // 1024 blocks x 4 chunks
    int tid = threadIdx.x;
    int lane = tid & 31, warp = tid >> 5;

    __shared__ float4 sW1[C0 * 4];    // [d<32][c4<4]
    __shared__ float4 sB1[4];
    __shared__ float4 sD0[C0];
    __shared__ float4 sRed[8 * 8];    // per-warp: 4 s + 4 q float4s

    for (int i = tid; i < C0 * 4; i += CH) sW1[i] = ((const float4*)W1)[i];
    if (tid < 4)  sB1[tid] = ((const float4*)b1)[tid];
    if (tid < C0) sD0[tid] = g_dice0[tid];
    __syncthreads();

    const ulonglong2* sW1_2 = (const ulonglong2*)sW1;
    const ulonglong2* sB1_2 = (const ulonglong2*)sB1;

    u64 s0=0,s1=0,s2=0,s3=0,s4=0,s5=0,s6=0,s7=0;
    u64 q0=0,q1=0,q2=0,q3=0,q4=0,q5=0,q6=0,q7=0;

    const uint4* sbase = &g_h0h[(size_t)blk * 4 * 1024 + warp * 128];

#pragma unroll
    for (int lc = 0; lc < 4; lc++) {
        const uint4* srcb = sbase + (size_t)lc * 1024;
        uint4 xA = __ldcs(&srcb[0*32+lane]);
        uint4 xB = __ldcs(&srcb[1*32+lane]);
        uint4 xC = __ldcs(&srcb[2*32+lane]);
        uint4 xD = __ldcs(&srcb[3*32+lane]);

        u64 b0,b1,b2,b3,b4,b5,b6,b7;
        { ulonglong2 t;
          t=sB1_2[0]; b0=t.x; b1=t.y;  t=sB1_2[1]; b2=t.x; b3=t.y;
          t=sB1_2[2]; b4=t.x; b5=t.y;  t=sB1_2[3]; b6=t.x; b7=t.y; }

        H1PAIR(xA.x, 0)  H1PAIR(xA.y, 2)  H1PAIR(xA.z, 4)  H1PAIR(xA.w, 6)
        H1PAIR(xB.x, 8)  H1PAIR(xB.y,10)  H1PAIR(xB.z,12)  H1PAIR(xB.w,14)
        H1PAIR(xC.x,16)  H1PAIR(xC.y,18)  H1PAIR(xC.z,20)  H1PAIR(xC.w,22)
        H1PAIR(xD.x,24)  H1PAIR(xD.y,26)  H1PAIR(xD.z,28)  H1PAIR(xD.w,30)

        size_t chunk = (size_t)blk * 4 + lc;
        uint4 pA = make_uint4(h2p(b0), h2p(b1), h2p(b2), h2p(b3));
        uint4 pB = make_uint4(h2p(b4), h2p(b5), h2p(b6), h2p(b7));
        uint4* dst = &g_h1h[chunk * 512 + warp * 64];
        __stcs(&dst[0*32+lane], pA); __stcs(&dst[1*32+lane], pB);

        add2(s0,b0); add2(s1,b1); add2(s2,b2); add2(s3,b3);
        add2(s4,b4); add2(s5,b5); add2(s6,b6); add2(s7,b7);
        fma2(q0,b0,b0); fma2(q1,b1,b1); fma2(q2,b2,b2); fma2(q3,b3,b3);
        fma2(q4,b4,b4); fma2(q5,b5,b5); fma2(q6,b6,b6); fma2(q7,b7,b7);
    }

    float4 S0,S1,S2,S3, Q0,Q1,Q2,Q3;
    unpack2(s0,S0.x,S0.y); unpack2(s1,S0.z,S0.w);  unpack2(s2,S1.x,S1.y); unpack2(s3,S1.z,S1.w);
    unpack2(s4,S2.x,S2.y); unpack2(s5,S2.z,S2.w);  unpack2(s6,S3.x,S3.y); unpack2(s7,S3.z,S3.w);
    unpack2(q0,Q0.x,Q0.y); unpack2(q1,Q0.z,Q0.w);  unpack2(q2,Q1.x,Q1.y); unpack2(q3,Q1.z,Q1.w);
    unpack2(q4,Q2.x,Q2.y); unpack2(q5,Q2.z,Q2.w);  unpack2(q6,Q3.x,Q3.y); unpack2(q7,Q3.z,Q3.w);

    SHRED(S0); SHRED(S1); SHRED(S2); SHRED(S3);
    SHRED(Q0); SHRED(Q1); SHRED(Q2); SHRED(Q3);
    if (lane == 0) {
        float4* r = &sRed[warp * 8];
        r[0]=S0; r[1]=S1; r[2]=S2; r[3]=S3;
        r[4]=Q0; r[5]=Q1; r[6]=Q2; r[7]=Q3;
    }
    __syncthreads();
    if (tid < 32) {
        const float* rf = (const float*)sRed;
        float s = 0.f;
#pragma unroll
        for (int w = 0; w < 8; w++) s += rf[w * 32 + tid];
        atomicAdd(&g_stats[64 + tid], (double)s);
    }
}

// ---------------- K4: finalize layer-1 batchnorm ----------------
__global__ void k_fin1(const float* __restrict__ a1) {
    int c = threadIdx.x;  // 16
    double m = g_stats[64 + c] / NTOT;
    double v = g_stats[80 + c] / NTOT - m * m;
    float rstd = (float)(1.0 / sqrt(v + 1e-9));
    float al = a1[c];
    g_dice1[c] = make_float4((float)m, rstd, al, 1.0f - al);
}

// ---------------- K5: score = dice1(h1)@wk + bk; out[b] += score * keys ----------------
__global__ void __launch_bounds__(CH) k_out(const float* __restrict__ keys,
                                            const float* __restrict__ wk,
                                            const float* __restrict__ bk,
                                            float* __restrict__ out) {
    int blk = blockIdx.x;             // 1024: 2 blocks per batch
    int b   = blk >> 1;
    int ck0 = (blk & 1) * 4;
    int tid = threadIdx.x;
    int lane = tid & 31, warp = tid >> 5;

    __shared__ float  sK[CH * 21];
    __shared__ float4 sD1[C1];
    __shared__ float4 sWk4[4];
    __shared__ float  sBk;
    __shared__ float4 sRed[8 * 5];

    if (tid < C1) sD1[tid] = g_dice1[tid];
    if (tid < 4)  sWk4[tid] = ((const float4*)wk)[tid];
    if (tid == 0) sBk = bk[0];

    float4 A0=F4Z,A1=F4Z,A2=F4Z,A3=F4Z,A4=F4Z;

    for (int lc = 0; lc < 4; lc++) {
        size_t chunk = (size_t)b * 8 + ck0 + lc;
        // issue independent h1 loads BEFORE the key-staging barrier
        const uint4* hb = &g_h1h[chunk * 512 + warp * 64];
        uint4 u0 = __ldcs(&hb[0*32+lane]);
        uint4 u1 = __ldcs(&hb[1*32+lane]);

        __syncthreads();
        stage_keys(sK, keys, chunk, tid);
        __syncthreads();

        float score = sBk;
        {
            float2 f;
            f = upkh(u0.x);
            score = fmaf(dice_f(f.x, sD1[ 0]), sWk4[0].x, score);
            score = fmaf(dice_f(f.y, sD1[ 1]), sWk4[0].y, score);
            f = upkh(u0.y);
            score = fmaf(dice_f(f.x, sD1[ 2]), sWk4[0].z, score);
            score = fmaf(dice_f(f.y, sD1[ 3]), sWk4[0].w, score);
            f = upkh(u0.z);
            score = fmaf(dice_f(f.x, sD1[ 4]), sWk4[1].x, score);
            score = fmaf(dice_f(f.y, sD1[ 5]), sWk4[1].y, score);
            f = upkh(u0.w);
            score = fmaf(dice_f(f.x, sD1[ 6]), sWk4[1].z, score);
            score = fmaf(dice_f(f.y, sD1[ 7]), sWk4[1].w, score);
            f = upkh(u1.x);
            score = fmaf(dice_f(f.x, sD1[ 8]), sWk4[2].x, score);
            score = fmaf(dice_f(f.y, sD1[ 9]), sWk4[2].y, score);
            f = upkh(u1.y);
            score = fmaf(dice_f(f.x, sD1[10]), sWk4[2].z, score);
            score = fmaf(dice_f(f.y, sD1[11]), sWk4[2].w, score);
            f = upkh(u1.z);
            score = fmaf(dice_f(f.x, sD1[12]), sWk4[3].x, score);
            score = fmaf(dice_f(f.y, sD1[13]), sWk4[3].y, score);
            f = upkh(u1.w);
            score = fmaf(dice_f(f.x, sD1[14]), sWk4[3].z, score);
            score = fmaf(dice_f(f.y, sD1[15]), sWk4[3].w, score);
        }

        const float* kr = &sK[tid * 21];
        A0.x=fmaf(score,kr[0],A0.x);  A0.y=fmaf(score,kr[1],A0.y);
        A0.z=fmaf(score,kr[2],A0.z);  A0.w=fmaf(score,kr[3],A0.w);
        A1.x=fmaf(score,kr[4],A1.x);  A1.y=fmaf(score,kr[5],A1.y);
        A1.z=fmaf(score,kr[6],A1.z);  A1.w=fmaf(score,kr[7],A1.w);
        A2.x=fmaf(score,kr[8],A2.x);  A2.y=fmaf(score,kr[9],A2.y);
        A2.z=fmaf(score,kr[10],A2.z); A2.w=fmaf(score,kr[11],A2.w);
        A3.x=fmaf(score,kr[12],A3.x); A3.y=fmaf(score,kr[13],A3.y);
        A3.z=fmaf(score,kr[14],A3.z); A3.w=fmaf(score,kr[15],A3.w);
        A4.x=fmaf(score,kr[16],A4.x); A4.y=fmaf(score,kr[17],A4.y);
        A4.z=fmaf(score,kr[18],A4.z); A4.w=fmaf(score,kr[19],A4.w);
    }

    SHRED(A0); SHRED(A1); SHRED(A2); SHRED(A3); SHRED(A4);
    if (lane == 0) {
        float4* r = &sRed[warp * 5];
        r[0]=A0; r[1]=A1; r[2]=A2; r[3]=A3; r[4]=A4;
    }
    __syncthreads();
    if (tid < DD) {
        const float* rf = (const float*)sRed;
        float s = 0.f;
#pragma unroll
        for (int w = 0; w < 8; w++) s += rf[w * 20 + tid];
        atomicAdd(&out[b * DD + tid], s);
    }
}

// ---------------- launch ----------------
extern "C" void kernel_launch(void* const* d_in, const int* in_sizes, int n_in,
                              void* d_out, int out_size) {
    const float* keys = (const float*)d_in[0];
    const float* q    = (const float*)d_in[1];
    /* d_in[2] = mask: dead in the reference (unmasked scores are used) */
    const float* W0   = (const float*)d_in[3];
    const float* b0   = (const float*)d_in[4];
    const float* a0   = (const float*)d_in[5];
    const float* W1   = (const float*)d_in[6];
    const float* b1   = (const float*)d_in[7];
    const float* a1   = (const float*)d_in[8];
    const float* wk   = (const float*)d_in[9];
    const float* bk   = (const float*)d_in[10];
    float* out = (float*)d_out;

    k_prep<<<BB, 32>>>(q, W0, b0, out);
    k_h0  <<<1024, CH>>>(keys);
    k_fin0<<<1, 32>>>(a0);
    k_h1  <<<1024, CH>>>(W1, b1);
    k_fin1<<<1, 16>>>(a1);
    k_out <<<1024, CH>>>(keys, wk, bk, out);
}